// round 4
// baseline (speedup 1.0000x reference)
#include <cuda_runtime.h>

#define NBX 168
#define NBY 480
#define NBL 6
#define EXT 2
#define WW 5
#define NBYP 496                      // padded y stride (mult of 4)
#define PADY 8                        // y guard offset
#define PLANE (NBX * NBYP)            // 83328
#define NDEM (NBL * PLANE)            // 499968
#define INV_SQRT2 0.70710678118654752440f
#define INV_CAP (1.0f / 16.0f)

__device__ __align__(16) float g_dem[NDEM];
__device__ __align__(16) float g_compat[NDEM];

__device__ __forceinline__ void red_add_v4(float* addr, float a, float b,
                                           float c, float d) {
    asm volatile("red.global.add.v4.f32 [%0], {%1, %2, %3, %4};"
                 :: "l"(addr), "f"(a), "f"(b), "f"(c), "f"(d) : "memory");
}

// ---------------------------------------------------------------------------
// Phase 0: zero demand map + output buffer (compat pads stay 0 automatically)
// ---------------------------------------------------------------------------
__global__ void zero_kernel(float* __restrict__ out, int out_n) {
    int i = blockIdx.x * blockDim.x + threadIdx.x;
    if (i < NDEM) g_dem[i] = 0.0f;
    if (i < out_n) out[i] = 0.0f;
}

// 5-wide x-axis weights via erf chain (6 erfs), zeroed when bin out of range.
__device__ __forceinline__ void axis_weights_x(float c, int& b0, float* g) {
    b0 = (int)floorf(c) - EXT;
    float ep = erff(((float)b0 - c) * INV_SQRT2);
#pragma unroll
    for (int k = 0; k < WW; k++) {
        float e = erff(((float)(b0 + k + 1) - c) * INV_SQRT2);
        int b = b0 + k;
        g[k] = (b >= 0 && b < NBX) ? 0.5f * (e - ep) : 0.0f;
        ep = e;
    }
}

// 8-slot aligned y-axis window: slots y4..y4+7 (y4 = 4-aligned), weight zero
// outside the 5-wide truncation window or the [0,NBY) range. 9 erfs.
__device__ __forceinline__ void axis_weights_y8(float c, int& y4, float* w) {
    int b0 = (int)floorf(c) - EXT;
    y4 = b0 & ~3;
    float ep = erff(((float)y4 - c) * INV_SQRT2);
#pragma unroll
    for (int s = 0; s < 8; s++) {
        int y = y4 + s;
        float e = erff(((float)(y + 1) - c) * INV_SQRT2);
        bool ok = (y >= b0) && (y <= b0 + EXT + EXT) && (y >= 0) && (y < NBY);
        w[s] = ok ? 0.5f * (e - ep) : 0.0f;
        ep = e;
    }
}

// ---------------------------------------------------------------------------
// Phase 1: scatter-add area * (gX outer gY) via vector reductions (ILP=1;
// REDs have no return latency, keep occupancy high)
// ---------------------------------------------------------------------------
__global__ void scatter_kernel(const float* __restrict__ pos,
                               const float* __restrict__ nsx,
                               const float* __restrict__ nsy,
                               const int*   __restrict__ lidx,
                               const int*   __restrict__ ltype,
                               int Lnum, int n) {
    int l = blockIdx.x * blockDim.x + threadIdx.x;
    if (l >= Lnum) return;
    int idx = lidx[l];
    float sx = nsx[idx];
    float sy = nsy[idx];
    float cx = pos[idx]     + 0.5f * sx;
    float cy = pos[n + idx] + 0.5f * sy;
    float area = sx * sy;
    int lt = ltype[idx];

    int bx0, y4;
    float wx[WW], wy[8];
    axis_weights_x(cx, bx0, wx);
    axis_weights_y8(cy, y4, wy);

#pragma unroll
    for (int i = 0; i < WW; i++) {
        float axi = area * wx[i];
        if (axi == 0.0f) continue;
        float* p = g_dem + ((lt * NBX + (bx0 + i)) * NBYP + PADY + y4);
        red_add_v4(p,     axi * wy[0], axi * wy[1], axi * wy[2], axi * wy[3]);
        red_add_v4(p + 4, axi * wy[4], axi * wy[5], axi * wy[6], axi * wy[7]);
    }
}

// ---------------------------------------------------------------------------
// Phase 2: compat[t,x,y] = sum_l frac[t,l] * dem[l,x,y]
// ---------------------------------------------------------------------------
__global__ void compat_kernel(const int* __restrict__ frac) {
    int p = blockIdx.x * blockDim.x + threadIdx.x;
    if (p >= PLANE) return;
    float d[NBL];
#pragma unroll
    for (int l = 0; l < NBL; l++) d[l] = g_dem[l * PLANE + p];
#pragma unroll
    for (int t = 0; t < NBL; t++) {
        float s = 0.0f;
#pragma unroll
        for (int l = 0; l < NBL; l++)
            s += (float)__ldg(&frac[t * NBL + l]) * d[l];
        g_compat[t * PLANE + p] = s;
    }
}

// ---------------------------------------------------------------------------
// Phase 3: gather compat under each window, 2 instances per thread for MLP
// ---------------------------------------------------------------------------
__device__ __forceinline__ void gather_one(const float* __restrict__ pos,
                                           const float* __restrict__ nsx,
                                           const float* __restrict__ nsy,
                                           const int*   __restrict__ lidx,
                                           const int*   __restrict__ ltype,
                                           float* __restrict__ out,
                                           int l, int n) {
    int idx = lidx[l];
    float sx = nsx[idx];
    float sy = nsy[idx];
    float cx = pos[idx]     + 0.5f * sx;
    float cy = pos[n + idx] + 0.5f * sy;
    int lt = ltype[idx];

    int bx0, y4;
    float wx[WW], wy[8];
    axis_weights_x(cx, bx0, wx);
    axis_weights_y8(cy, y4, wy);

    const float* base = g_compat + (lt * NBX + bx0) * NBYP + PADY + y4;
    // Issue all 10 vector loads up front for MLP
    float4 a[WW], b[WW];
#pragma unroll
    for (int i = 0; i < WW; i++) {
        // clamp row into valid x range so OOB rows (wx==0) still load safely
        int xr = bx0 + i;
        xr = xr < 0 ? 0 : (xr >= NBX ? NBX - 1 : xr);
        const float4* p = (const float4*)(base + (xr - bx0) * NBYP);
        a[i] = p[0];
        b[i] = p[1];
    }
    float s = 0.0f;
#pragma unroll
    for (int i = 0; i < WW; i++) {
        float sj = a[i].x * wy[0] + a[i].y * wy[1] + a[i].z * wy[2] + a[i].w * wy[3]
                 + b[i].x * wy[4] + b[i].y * wy[5] + b[i].z * wy[6] + b[i].w * wy[7];
        s += wx[i] * sj;
    }
    out[idx] = s * INV_CAP;
}

__global__ void gather_kernel(const float* __restrict__ pos,
                              const float* __restrict__ nsx,
                              const float* __restrict__ nsy,
                              const int*   __restrict__ lidx,
                              const int*   __restrict__ ltype,
                              float* __restrict__ out,
                              int Lnum, int n) {
    int t = blockIdx.x * blockDim.x + threadIdx.x;
    int l0 = t * 2;
    if (l0 >= Lnum) return;
    gather_one(pos, nsx, nsy, lidx, ltype, out, l0, n);
    if (l0 + 1 < Lnum)
        gather_one(pos, nsx, nsy, lidx, ltype, out, l0 + 1, n);
}

// ---------------------------------------------------------------------------
extern "C" void kernel_launch(void* const* d_in, const int* in_sizes, int n_in,
                              void* d_out, int out_size) {
    const float* pos   = (const float*)d_in[0];
    const float* nsx   = (const float*)d_in[1];
    const float* nsy   = (const float*)d_in[2];
    const int*   lidx  = (const int*)d_in[3];
    const int*   ltype = (const int*)d_in[4];
    const int*   frac  = (const int*)d_in[5];
    float* out = (float*)d_out;

    int n    = in_sizes[1];   // number of nodes (2M)
    int Lnum = in_sizes[3];   // number of instances (1M)

    {
        int tot = out_size > NDEM ? out_size : NDEM;
        zero_kernel<<<(tot + 255) / 256, 256>>>(out, out_size);
    }
    scatter_kernel<<<(Lnum + 255) / 256, 256>>>(pos, nsx, nsy, lidx, ltype,
                                                Lnum, n);
    compat_kernel<<<(PLANE + 255) / 256, 256>>>(frac);
    {
        int threads = (Lnum + 1) / 2;
        gather_kernel<<<(threads + 255) / 256, 256>>>(pos, nsx, nsy, lidx,
                                                      ltype, out, Lnum, n);
    }
}

// round 5
// speedup vs baseline: 1.1575x; 1.1575x over previous
#include <cuda_runtime.h>
#include <cuda_fp16.h>

#define NBX 168
#define NBY 480
#define NBL 6
#define EXT 2
#define WW 5
#define NBYP 496                      // padded y stride (mult of 8)
#define PADY 8                        // y guard offset (mult of 8)
#define PLANE (NBX * NBYP)            // 83328 (mult of 8)
#define NDEM (NBL * PLANE)            // 499968
#define INV_SQRT2 0.70710678118654752440f
#define INV_CAP (1.0f / 16.0f)

__device__ __align__(16) float  g_dem[NDEM];
__device__ __align__(16) __half g_compatA[NDEM];   // value at slot y
__device__ __align__(16) __half g_compatB[NDEM];   // B[y'] = A[y'+4]

__device__ __forceinline__ void red_add_v4(float* addr, float a, float b,
                                           float c, float d) {
    asm volatile("red.global.add.v4.f32 [%0], {%1, %2, %3, %4};"
                 :: "l"(addr), "f"(a), "f"(b), "f"(c), "f"(d) : "memory");
}

// ---------------------------------------------------------------------------
// Phase 0: zero demand map, compatB (its 4-slot tails are never written),
// and the output buffer.
// ---------------------------------------------------------------------------
__global__ void zero_kernel(float* __restrict__ out, int out_n) {
    int i = blockIdx.x * blockDim.x + threadIdx.x;
    if (i < NDEM) g_dem[i] = 0.0f;
    if (i < NDEM / 2) ((unsigned*)g_compatB)[i] = 0u;
    if (i < out_n) out[i] = 0.0f;
}

// 5-wide x-axis weights via erf chain (6 erfs), zeroed when bin out of range.
__device__ __forceinline__ void axis_weights_x(float c, int& b0, float* g) {
    b0 = (int)floorf(c) - EXT;
    float ep = erff(((float)b0 - c) * INV_SQRT2);
#pragma unroll
    for (int k = 0; k < WW; k++) {
        float e = erff(((float)(b0 + k + 1) - c) * INV_SQRT2);
        int b = b0 + k;
        g[k] = (b >= 0 && b < NBX) ? 0.5f * (e - ep) : 0.0f;
        ep = e;
    }
}

// 8-slot aligned y-axis window: slots y4..y4+7 (y4 = 4-aligned), weight zero
// outside the 5-wide truncation window or the [0,NBY) range. 9 erfs.
__device__ __forceinline__ void axis_weights_y8(float c, int& y4, float* w) {
    int b0 = (int)floorf(c) - EXT;
    y4 = b0 & ~3;
    float ep = erff(((float)y4 - c) * INV_SQRT2);
#pragma unroll
    for (int s = 0; s < 8; s++) {
        int y = y4 + s;
        float e = erff(((float)(y + 1) - c) * INV_SQRT2);
        bool ok = (y >= b0) && (y <= b0 + EXT + EXT) && (y >= 0) && (y < NBY);
        w[s] = ok ? 0.5f * (e - ep) : 0.0f;
        ep = e;
    }
}

// ---------------------------------------------------------------------------
// Phase 1: scatter-add area * (gX outer gY) via fp32 vector reductions
// ---------------------------------------------------------------------------
__global__ void scatter_kernel(const float* __restrict__ pos,
                               const float* __restrict__ nsx,
                               const float* __restrict__ nsy,
                               const int*   __restrict__ lidx,
                               const int*   __restrict__ ltype,
                               int Lnum, int n) {
    int l = blockIdx.x * blockDim.x + threadIdx.x;
    if (l >= Lnum) return;
    int idx = lidx[l];
    float sx = nsx[idx];
    float sy = nsy[idx];
    float cx = pos[idx]     + 0.5f * sx;
    float cy = pos[n + idx] + 0.5f * sy;
    float area = sx * sy;
    int lt = ltype[idx];

    int bx0, y4;
    float wx[WW], wy[8];
    axis_weights_x(cx, bx0, wx);
    axis_weights_y8(cy, y4, wy);

#pragma unroll
    for (int i = 0; i < WW; i++) {
        float axi = area * wx[i];
        if (axi == 0.0f) continue;
        float* p = g_dem + ((lt * NBX + (bx0 + i)) * NBYP + PADY + y4);
        red_add_v4(p,     axi * wy[0], axi * wy[1], axi * wy[2], axi * wy[3]);
        red_add_v4(p + 4, axi * wy[4], axi * wy[5], axi * wy[6], axi * wy[7]);
    }
}

// ---------------------------------------------------------------------------
// Phase 2: compat[t,x,y] = sum_l frac[t,l] * dem[l,x,y], written as fp16
// into two copies: A at slot y, B at slot y-4 (shifted for alignment).
// ---------------------------------------------------------------------------
__global__ void compat_kernel(const int* __restrict__ frac) {
    int p = blockIdx.x * blockDim.x + threadIdx.x;
    if (p >= PLANE) return;
    int ymod = p % NBYP;
    float d[NBL];
#pragma unroll
    for (int l = 0; l < NBL; l++) d[l] = g_dem[l * PLANE + p];
#pragma unroll
    for (int t = 0; t < NBL; t++) {
        float s = 0.0f;
#pragma unroll
        for (int l = 0; l < NBL; l++)
            s += (float)__ldg(&frac[t * NBL + l]) * d[l];
        __half h = __float2half_rn(s);
        g_compatA[t * PLANE + p] = h;
        if (ymod >= 4) g_compatB[t * PLANE + p - 4] = h;
    }
}

// ---------------------------------------------------------------------------
// Phase 3: gather fp16 compat: ONE 128-bit load per x-row (5 wavefronts/inst)
// ---------------------------------------------------------------------------
__global__ void gather_kernel(const float* __restrict__ pos,
                              const float* __restrict__ nsx,
                              const float* __restrict__ nsy,
                              const int*   __restrict__ lidx,
                              const int*   __restrict__ ltype,
                              float* __restrict__ out,
                              int Lnum, int n) {
    int l = blockIdx.x * blockDim.x + threadIdx.x;
    if (l >= Lnum) return;
    int idx = lidx[l];
    float sx = nsx[idx];
    float sy = nsy[idx];
    float cx = pos[idx]     + 0.5f * sx;
    float cy = pos[n + idx] + 0.5f * sy;
    int lt = ltype[idx];

    int bx0, y4;
    float wx[WW], wy[8];
    axis_weights_x(cx, bx0, wx);
    axis_weights_y8(cy, y4, wy);

    // Select the copy where the 8-half window is 16B-aligned.
    const __half* map;
    int slot;
    if (y4 & 4) { map = g_compatB; slot = y4 - 4; }
    else        { map = g_compatA; slot = y4;     }
    const __half* base = map + (lt * NBX + bx0) * NBYP + PADY + slot;

    // Issue all 5 vector loads up front (rows clamped so OOB rows with
    // wx==0 still read in-bounds memory).
    uint4 v[WW];
#pragma unroll
    for (int i = 0; i < WW; i++) {
        int xr = bx0 + i;
        xr = xr < 0 ? 0 : (xr >= NBX ? NBX - 1 : xr);
        v[i] = *(const uint4*)(base + (xr - bx0) * NBYP);
    }

    float s = 0.0f;
#pragma unroll
    for (int i = 0; i < WW; i++) {
        float2 c0 = __half22float2(*(const __half2*)&v[i].x);
        float2 c1 = __half22float2(*(const __half2*)&v[i].y);
        float2 c2 = __half22float2(*(const __half2*)&v[i].z);
        float2 c3 = __half22float2(*(const __half2*)&v[i].w);
        float sj = c0.x * wy[0] + c0.y * wy[1] + c1.x * wy[2] + c1.y * wy[3]
                 + c2.x * wy[4] + c2.y * wy[5] + c3.x * wy[6] + c3.y * wy[7];
        s += wx[i] * sj;
    }
    out[idx] = s * INV_CAP;
}

// ---------------------------------------------------------------------------
extern "C" void kernel_launch(void* const* d_in, const int* in_sizes, int n_in,
                              void* d_out, int out_size) {
    const float* pos   = (const float*)d_in[0];
    const float* nsx   = (const float*)d_in[1];
    const float* nsy   = (const float*)d_in[2];
    const int*   lidx  = (const int*)d_in[3];
    const int*   ltype = (const int*)d_in[4];
    const int*   frac  = (const int*)d_in[5];
    float* out = (float*)d_out;

    int n    = in_sizes[1];   // number of nodes (2M)
    int Lnum = in_sizes[3];   // number of instances (1M)

    {
        int tot = out_size > NDEM ? out_size : NDEM;
        zero_kernel<<<(tot + 255) / 256, 256>>>(out, out_size);
    }
    scatter_kernel<<<(Lnum + 255) / 256, 256>>>(pos, nsx, nsy, lidx, ltype,
                                                Lnum, n);
    compat_kernel<<<(PLANE + 255) / 256, 256>>>(frac);
    gather_kernel<<<(Lnum + 255) / 256, 256>>>(pos, nsx, nsy, lidx, ltype,
                                               out, Lnum, n);
}